// round 12
// baseline (speedup 1.0000x reference)
#include <cuda_runtime.h>
#include <math.h>

#define NN 50000
#define EE 800000
#define F 32
#define H 64
#define NINVC 128
#define GMAX 2048
#define EPSF 1e-6f
#define TILE 64

// ---------------- scratch (device globals; no allocation) ----------------
__device__ float4 d_sv[NN * F];    // packed node state {s, vx, vy, vz}
__device__ float4 d_acc[NN * F];   // packed accumulator {as, avx, avy, avz}
__device__ float d_cnt[NN];
__device__ float4 d_e1[EE];        // {dist, ea0, ea1, ea2}
__device__ float4 d_e2[EE];        // {ea3, ux, uy, uz}
__device__ float d_xgsum[GMAX * NINVC];
__device__ float d_gcnt[GMAX];
__device__ float d_xg[GMAX * NINVC];
__device__ float d_z1[GMAX * NINVC];
__device__ float d_m1[NINVC];
__device__ float d_r1[NINVC];
__device__ float d_m2[NINVC];
__device__ float d_r2[NINVC];

__device__ __forceinline__ float elu1(float x) { return x > 0.f ? x : expm1f(x); }

__device__ __forceinline__ void red_add_v4(float4* addr, float a, float b, float c, float d) {
    asm volatile("red.global.add.v4.f32 [%0], {%1, %2, %3, %4};"
                 :: "l"(addr), "f"(a), "f"(b), "f"(c), "f"(d) : "memory");
}

#define FMA2(acc, a, b) \
    asm("fma.rn.f32x2 %0, %1, %2, %0;" : "+l"(acc) : "l"(a), "l"(b))

#define PACK2(out, v) \
    asm("mov.b64 %0, {%1, %1};" : "=l"(out) : "r"(__float_as_uint(v)))

// ---------------- zero accumulators ----------------
__global__ void zero_kernel() {
    int stride = gridDim.x * blockDim.x;
    float4 z4 = make_float4(0.f, 0.f, 0.f, 0.f);
    for (int i = blockIdx.x * blockDim.x + threadIdx.x; i < NN * F; i += stride) {
        d_acc[i] = z4;
        if (i < NN) d_cnt[i] = 0.f;
        if (i < GMAX * NINVC) d_xgsum[i] = 0.f;
        if (i < GMAX) d_gcnt[i] = 0.f;
    }
}

// ---------------- one-time edge geometry + degree ----------------
__global__ void prep_kernel(const float* __restrict__ pos, const int* __restrict__ ei,
                            const float* __restrict__ ea, int E) {
    int e = blockIdx.x * blockDim.x + threadIdx.x;
    if (e >= E) return;
    int sn = ei[e], dn = ei[E + e];
    float dx = pos[dn * 3 + 0] - pos[sn * 3 + 0];
    float dy = pos[dn * 3 + 1] - pos[sn * 3 + 1];
    float dz = pos[dn * 3 + 2] - pos[sn * 3 + 2];
    float dist = sqrtf(dx * dx + dy * dy + dz * dz + EPSF);
    float4 eav = *(const float4*)&ea[e * 4];
    d_e1[e] = make_float4(dist, eav.x, eav.y, eav.z);
    float inv = 1.f / dist;
    d_e2[e] = make_float4(eav.w, dx * inv, dy * inv, dz * inv);
    atomicAdd(&d_cnt[dn], 1.f);
}

// ---------------- embedding ----------------
__global__ void embed_kernel(const float* __restrict__ x, const float* __restrict__ pos,
                             const float* __restrict__ Wes, const float* __restrict__ bes,
                             const float* __restrict__ Wev, int Nn) {
    int idx = blockIdx.x * blockDim.x + threadIdx.x;
    if (idx >= Nn * F) return;
    int n = idx / F, f = idx & (F - 1);
    float xs[5];
#pragma unroll
    for (int i = 0; i < 5; i++) xs[i] = x[n * 5 + i];
    float as = bes[f], av = 0.f;
#pragma unroll
    for (int i = 0; i < 5; i++) { as += xs[i] * Wes[i * F + f]; av += xs[i] * Wev[i * F + f]; }
    float px = pos[n * 3], py = pos[n * 3 + 1], pz = pos[n * 3 + 2];
    d_sv[idx] = make_float4(as, av * px, av * py, av * pz);
}

// ---------------- fused edge MLP + message + scatter (per layer) ----------------
// 64-edge tile, warp owns 8 edges, lane = feature f; precomputed edge geometry.
__global__ void __launch_bounds__(256, 4) msg_kernel(
    const int* __restrict__ ei,
    const float* __restrict__ W1, const float* __restrict__ b1,
    const float* __restrict__ W2, const float* __restrict__ b2, int E) {
    __shared__ float sW1[5 * H];        // 320
    __shared__ float sb1[H];            // 64
    __shared__ float sW2P[H * 96];      // 6144 : [k/2][col][2] paired over k
    __shared__ float sb2[3 * F];        // 96
    __shared__ float sEIn[TILE * 5];    // 320
    __shared__ float4 sU4[TILE];        // 256
    __shared__ int2 sSD[TILE];          // 128
    __shared__ float h1T[H * TILE];     // 4096 : [k][e]

    int tid = threadIdx.x;
    for (int i = tid; i < 5 * H; i += 256) sW1[i] = W1[i];
    if (tid < H) sb1[tid] = b1[tid];
    if (tid < 96) sb2[tid] = b2[tid];
    // paired layout: sW2P[k2*192 + col*2 + kk] = W2[(k2*2+kk)*96 + col]
    for (int i = tid; i < H * 96; i += 256) {
        int k2 = i / 192, r = i % 192, col = r >> 1, kk = r & 1;
        sW2P[i] = W2[(k2 * 2 + kk) * 96 + col];
    }

    int w = tid >> 5;       // warp 0..7
    int f = tid & 31;       // lane = feature
    int eBase = w * 8;      // warp owns 8 edges

    int ntiles = (E + TILE - 1) / TILE;
    for (int t = blockIdx.x; t < ntiles; t += gridDim.x) {
        int e0 = t * TILE;
        __syncthreads();  // previous tile consumed; weights visible
        if (tid < TILE) {
            int e = e0 + tid;
            if (e < E) {
                sSD[tid] = make_int2(ei[e], ei[E + e]);
                float4 e1 = d_e1[e];
                float4 e2 = d_e2[e];
                sEIn[tid * 5 + 0] = e1.x;
                sEIn[tid * 5 + 1] = e1.y;
                sEIn[tid * 5 + 2] = e1.z;
                sEIn[tid * 5 + 3] = e1.w;
                sEIn[tid * 5 + 4] = e2.x;
                sU4[tid] = make_float4(e2.y, e2.z, e2.w, 0.f);
            } else {
                sSD[tid] = make_int2(0, 0);
#pragma unroll
                for (int i = 0; i < 5; i++) sEIn[tid * 5 + i] = 0.f;
                sU4[tid] = make_float4(0.f, 0.f, 0.f, 0.f);
            }
        }
        __syncthreads();

        // GEMM1: h1T[c][e] = elu(b1[c] + edge_in[e] . W1[:,c])
        {
            int e = tid & (TILE - 1);
            int ch = tid >> 6;  // 0..3 -> 16 cols each
            float ein[5];
#pragma unroll
            for (int i = 0; i < 5; i++) ein[i] = sEIn[e * 5 + i];
#pragma unroll
            for (int cc = 0; cc < 16; cc++) {
                int c = ch * 16 + cc;
                float a = sb1[c];
#pragma unroll
                for (int i = 0; i < 5; i++) a += ein[i] * sW1[i * H + c];
                h1T[c * TILE + e] = a > 0.f ? a : (__expf(a) - 1.f);
            }
        }
        __syncthreads();

        // GEMM2 (64 -> 96): 8 edges/warp as 4 f32x2 pairs; k processed 2 at a time.
        unsigned long long aS[4], aV[4], aX[4];
        {
            unsigned long long bs, bv, bx;
            PACK2(bs, sb2[f]); PACK2(bv, sb2[F + f]); PACK2(bx, sb2[2 * F + f]);
#pragma unroll
            for (int p = 0; p < 4; p++) { aS[p] = bs; aV[p] = bv; aX[p] = bx; }
        }
#pragma unroll 4
        for (int k2 = 0; k2 < H / 2; k2++) {
            const float* wp = &sW2P[k2 * 192];
            float2 wsp = *(const float2*)&wp[f * 2];              // out=f,    k,k+1
            float2 wvp = *(const float2*)&wp[(F + f) * 2];        // out=32+f
            float2 wxp = *(const float2*)&wp[(2 * F + f) * 2];    // out=64+f
#pragma unroll
            for (int kk = 0; kk < 2; kk++) {
                const float* hrow = &h1T[(k2 * 2 + kk) * TILE + eBase];
                ulonglong2 hA = *(const ulonglong2*)(hrow);       // edges 0-3
                ulonglong2 hB = *(const ulonglong2*)(hrow + 4);   // edges 4-7
                unsigned long long ws2, wv2, wx2;
                PACK2(ws2, kk ? wsp.y : wsp.x);
                PACK2(wv2, kk ? wvp.y : wvp.x);
                PACK2(wx2, kk ? wxp.y : wxp.x);
                FMA2(aS[0], hA.x, ws2); FMA2(aS[1], hA.y, ws2);
                FMA2(aS[2], hB.x, ws2); FMA2(aS[3], hB.y, ws2);
                FMA2(aV[0], hA.x, wv2); FMA2(aV[1], hA.y, wv2);
                FMA2(aV[2], hB.x, wv2); FMA2(aV[3], hB.y, wv2);
                FMA2(aX[0], hA.x, wx2); FMA2(aX[1], hA.y, wx2);
                FMA2(aX[2], hB.x, wx2); FMA2(aX[3], hB.y, wx2);
            }
        }

        // messages + scatter: per edge, lanes = f -> coalesced LDG.128 + RED.v4
#pragma unroll
        for (int p = 0; p < 4; p++) {
            unsigned int gsl, gsh, gvl, gvh, gxl, gxh;
            asm("mov.b64 {%0, %1}, %2;" : "=r"(gsl), "=r"(gsh) : "l"(aS[p]));
            asm("mov.b64 {%0, %1}, %2;" : "=r"(gvl), "=r"(gvh) : "l"(aV[p]));
            asm("mov.b64 {%0, %1}, %2;" : "=r"(gxl), "=r"(gxh) : "l"(aX[p]));
#pragma unroll
            for (int half = 0; half < 2; half++) {
                int e = eBase + p * 2 + half;
                if (e0 + e >= E) continue;
                float gs = __uint_as_float(half ? gsh : gsl);
                float gv = __uint_as_float(half ? gvh : gvl);
                float gx = __uint_as_float(half ? gxh : gxl);
                int2 sd = sSD[e];
                float4 u = sU4[e];
                float4 sv = d_sv[sd.x * F + f];   // coalesced across lanes
                float c = gx * sv.x;
                red_add_v4(&d_acc[sd.y * F + f],  // coalesced across lanes
                           gs * sv.x,
                           gv * sv.y + c * u.x,
                           gv * sv.z + c * u.y,
                           gv * sv.w + c * u.z);
            }
        }
    }
}

// ---------------- node update: s += elu(as@Ws); v += av@Wv ----------------
__global__ void __launch_bounds__(256) upd_kernel(const float* __restrict__ Ws,
                                                  const float* __restrict__ Wv, int Nn) {
    __shared__ float sWs[F * F], sWv[F * F];
    __shared__ float4 sA[8][F];
    int tid = threadIdx.x;
    for (int i = tid; i < F * F; i += 256) { sWs[i] = Ws[i]; sWv[i] = Wv[i]; }
    int ln = tid >> 5, f = tid & 31;
    int n = blockIdx.x * 8 + ln;
    bool ok = n < Nn;
    if (ok) {
        float inv = 1.f / fmaxf(d_cnt[n], 1.f);
        float4 a = d_acc[n * F + f];
        sA[ln][f] = make_float4(a.x * inv, a.y * inv, a.z * inv, a.w * inv);
        d_acc[n * F + f] = make_float4(0.f, 0.f, 0.f, 0.f);  // ready for next layer
    }
    __syncthreads();
    if (ok) {
        float a = 0, vx = 0, vy = 0, vz = 0;
#pragma unroll
        for (int g = 0; g < F; g++) {
            float w1 = sWs[g * F + f], w2 = sWv[g * F + f];
            float4 ag = sA[ln][g];
            a  += ag.x * w1;
            vx += ag.y * w2;
            vy += ag.z * w2;
            vz += ag.w * w2;
        }
        float4 cur = d_sv[n * F + f];
        cur.x += elu1(a);
        cur.y += vx;
        cur.z += vy;
        cur.w += vz;
        d_sv[n * F + f] = cur;
    }
}

// ---------------- graph node counts ----------------
__global__ void gcnt_kernel(const int* __restrict__ batch, int Nn) {
    int n = blockIdx.x * blockDim.x + threadIdx.x;
    if (n < Nn) atomicAdd(&d_gcnt[batch[n]], 1.f);
}

// ---------------- invariant map + graph-sum pooling ----------------
__global__ void __launch_bounds__(128) inv_kernel(const int* __restrict__ batch,
                                                  const float* __restrict__ Winv,
                                                  const float* __restrict__ binv, int Nn) {
    __shared__ float sW[2 * F * NINVC];  // 32KB
    __shared__ float sFeat[2 * F];
    int tid = threadIdx.x;
    for (int i = tid; i < 2 * F * NINVC; i += 128) sW[i] = Winv[i];
    float bj = binv[tid];
    int n0 = blockIdx.x * 32;
    for (int nn = 0; nn < 32; nn++) {
        int n = n0 + nn;
        if (n >= Nn) break;
        __syncthreads();
        if (tid < F) {
            float4 sv = d_sv[n * F + tid];
            sFeat[tid] = sv.x;
            sFeat[F + tid] = sqrtf(sv.y * sv.y + sv.z * sv.z + sv.w * sv.w + EPSF);
        }
        __syncthreads();
        float acc = bj;
#pragma unroll 8
        for (int i = 0; i < 2 * F; i++) acc += sFeat[i] * sW[i * NINVC + tid];
        atomicAdd(&d_xgsum[batch[n] * NINVC + tid], acc);
    }
}

// ---------------- mean pool finalize ----------------
__global__ void poolfin_kernel(int G) {
    int i = blockIdx.x * blockDim.x + threadIdx.x;
    if (i < G * NINVC) d_xg[i] = d_xgsum[i] / fmaxf(d_gcnt[i / NINVC], 1.f);
}

// ---------------- batchnorm column stats ----------------
__global__ void bnstats_kernel(int which, int G) {
    const float* z = which ? d_z1 : d_xg;
    float* mean = which ? d_m2 : d_m1;
    float* rstd = which ? d_r2 : d_r1;
    int j = blockIdx.x;
    __shared__ float sS[256], sQ[256];
    float s = 0.f, q = 0.f;
    for (int g = threadIdx.x; g < G; g += 256) {
        float val = z[g * NINVC + j];
        s += val; q += val * val;
    }
    sS[threadIdx.x] = s; sQ[threadIdx.x] = q;
    __syncthreads();
    for (int off = 128; off > 0; off >>= 1) {
        if (threadIdx.x < off) { sS[threadIdx.x] += sS[threadIdx.x + off]; sQ[threadIdx.x] += sQ[threadIdx.x + off]; }
        __syncthreads();
    }
    if (threadIdx.x == 0) {
        float m = sS[0] / (float)G;
        float var = sQ[0] / (float)G - m * m;
        mean[j] = m;
        rstd[j] = rsqrtf(var + 1e-5f);
    }
}

// ---------------- fc1 ----------------
__global__ void __launch_bounds__(128) fc1_kernel(const float* __restrict__ Wf1,
                                                  const float* __restrict__ bf1,
                                                  const float* __restrict__ g1,
                                                  const float* __restrict__ be1, int G) {
    __shared__ float sA[NINVC];
    int tid = threadIdx.x;
    float gj = g1[tid], bej = be1[tid], mj = d_m1[tid], rj = d_r1[tid], bfj = bf1[tid];
    int r0 = blockIdx.x * 16;
    for (int rr = 0; rr < 16; rr++) {
        int r = r0 + rr;
        if (r >= G) break;
        __syncthreads();
        float a = (d_xg[r * NINVC + tid] - mj) * rj * gj + bej;
        sA[tid] = elu1(a);
        __syncthreads();
        float acc = bfj;
#pragma unroll 8
        for (int i = 0; i < NINVC; i++) acc += sA[i] * Wf1[i * NINVC + tid];
        d_z1[r * NINVC + tid] = acc;
    }
}

// ---------------- fc2 ----------------
__global__ void fc2_kernel(const float* __restrict__ Wf2, const float* __restrict__ bf2,
                           const float* __restrict__ g2, const float* __restrict__ be2,
                           float* __restrict__ out, int G) {
    int warp = threadIdx.x >> 5, lane = threadIdx.x & 31;
    int r = blockIdx.x * 8 + warp;
    if (r >= G) return;
    float acc = 0.f;
    for (int j = lane; j < NINVC; j += 32) {
        float a = (d_z1[r * NINVC + j] - d_m2[j]) * d_r2[j] * g2[j] + be2[j];
        acc += elu1(a) * Wf2[j];
    }
#pragma unroll
    for (int off = 16; off > 0; off >>= 1) acc += __shfl_down_sync(0xffffffffu, acc, off);
    if (lane == 0) out[r] = acc + bf2[0];
}

// ---------------- launch ----------------
extern "C" void kernel_launch(void* const* d_in, const int* in_sizes, int n_in,
                              void* d_out, int out_size) {
    const float* x     = (const float*)d_in[0];
    const float* pos   = (const float*)d_in[1];
    const int*   ei    = (const int*)d_in[2];
    const float* ea    = (const float*)d_in[3];
    const int*   batch = (const int*)d_in[4];
    const float* Wes   = (const float*)d_in[5];
    const float* bes   = (const float*)d_in[6];
    const float* Wev   = (const float*)d_in[7];
    const float* W1    = (const float*)d_in[8];
    const float* b1    = (const float*)d_in[9];
    const float* W2    = (const float*)d_in[10];
    const float* b2    = (const float*)d_in[11];
    const float* Ws    = (const float*)d_in[12];
    const float* Wv    = (const float*)d_in[13];
    const float* Winv  = (const float*)d_in[14];
    const float* binv  = (const float*)d_in[15];
    const float* g1    = (const float*)d_in[16];
    const float* be1   = (const float*)d_in[17];
    const float* Wf1   = (const float*)d_in[18];
    const float* bf1   = (const float*)d_in[19];
    const float* g2    = (const float*)d_in[20];
    const float* be2   = (const float*)d_in[21];
    const float* Wf2   = (const float*)d_in[22];
    const float* bf2   = (const float*)d_in[23];

    int Nn = in_sizes[0] / 5;
    int E  = in_sizes[2] / 2;
    int G  = out_size;
    float* out = (float*)d_out;

    zero_kernel<<<2048, 256>>>();
    prep_kernel<<<(E + 255) / 256, 256>>>(pos, ei, ea, E);
    embed_kernel<<<(Nn * F + 255) / 256, 256>>>(x, pos, Wes, bes, Wev, Nn);

    for (int l = 0; l < 4; l++) {
        msg_kernel<<<1480, 256>>>(ei,
                                  W1 + l * 5 * H, b1 + l * H,
                                  W2 + l * H * 3 * F, b2 + l * 3 * F, E);
        upd_kernel<<<(Nn + 7) / 8, 256>>>(Ws + l * F * F, Wv + l * F * F, Nn);
    }

    gcnt_kernel<<<(Nn + 255) / 256, 256>>>(batch, Nn);
    inv_kernel<<<(Nn + 31) / 32, 128>>>(batch, Winv, binv, Nn);
    poolfin_kernel<<<(G * NINVC + 255) / 256, 256>>>(G);
    bnstats_kernel<<<NINVC, 256>>>(0, G);
    fc1_kernel<<<(G + 15) / 16, 128>>>(Wf1, bf1, g1, be1, G);
    bnstats_kernel<<<NINVC, 256>>>(1, G);
    fc2_kernel<<<(G + 7) / 8, 256>>>(Wf2, bf2, g2, be2, out, G);
}

// round 13
// speedup vs baseline: 1.1785x; 1.1785x over previous
#include <cuda_runtime.h>
#include <math.h>

#define NN 50000
#define EE 800000
#define F 32
#define H 64
#define NINVC 128
#define GMAX 2048
#define EPSF 1e-6f
#define TILE 64

// ---------------- scratch (device globals; no allocation) ----------------
__device__ float4 d_sv[NN * F];    // packed node state {s, vx, vy, vz}
__device__ float4 d_acc[NN * F];   // packed accumulator {as, avx, avy, avz}
__device__ float d_cnt[NN];
__device__ float4 d_e1[EE];        // {dist, ea0, ea1, ea2}
__device__ float4 d_e2[EE];        // {ea3, ux, uy, uz}
__device__ float d_xgsum[GMAX * NINVC];
__device__ float d_gcnt[GMAX];
__device__ float d_xg[GMAX * NINVC];
__device__ float d_z1[GMAX * NINVC];
__device__ float d_m1[NINVC];
__device__ float d_r1[NINVC];
__device__ float d_m2[NINVC];
__device__ float d_r2[NINVC];

__device__ __forceinline__ float elu1(float x) { return x > 0.f ? x : expm1f(x); }

__device__ __forceinline__ void red_add_v4(float4* addr, float a, float b, float c, float d) {
    asm volatile("red.global.add.v4.f32 [%0], {%1, %2, %3, %4};"
                 :: "l"(addr), "f"(a), "f"(b), "f"(c), "f"(d) : "memory");
}

__device__ __forceinline__ unsigned int to_tf32(float x) {
    unsigned int u;
    asm("cvt.rna.tf32.f32 %0, %1;" : "=r"(u) : "f"(x));
    return u;
}

__device__ __forceinline__ void mma_tf32(float& c0, float& c1, float& c2, float& c3,
                                         unsigned int a0, unsigned int a1,
                                         unsigned int a2, unsigned int a3,
                                         unsigned int b0, unsigned int b1) {
    asm volatile(
        "mma.sync.aligned.m16n8k8.row.col.f32.tf32.tf32.f32 "
        "{%0,%1,%2,%3}, {%4,%5,%6,%7}, {%8,%9}, {%0,%1,%2,%3};"
        : "+f"(c0), "+f"(c1), "+f"(c2), "+f"(c3)
        : "r"(a0), "r"(a1), "r"(a2), "r"(a3), "r"(b0), "r"(b1));
}

// ---------------- zero accumulators ----------------
__global__ void zero_kernel() {
    int stride = gridDim.x * blockDim.x;
    float4 z4 = make_float4(0.f, 0.f, 0.f, 0.f);
    for (int i = blockIdx.x * blockDim.x + threadIdx.x; i < NN * F; i += stride) {
        d_acc[i] = z4;
        if (i < NN) d_cnt[i] = 0.f;
        if (i < GMAX * NINVC) d_xgsum[i] = 0.f;
        if (i < GMAX) d_gcnt[i] = 0.f;
    }
}

// ---------------- one-time edge geometry + degree ----------------
__global__ void prep_kernel(const float* __restrict__ pos, const int* __restrict__ ei,
                            const float* __restrict__ ea, int E) {
    int e = blockIdx.x * blockDim.x + threadIdx.x;
    if (e >= E) return;
    int sn = ei[e], dn = ei[E + e];
    float dx = pos[dn * 3 + 0] - pos[sn * 3 + 0];
    float dy = pos[dn * 3 + 1] - pos[sn * 3 + 1];
    float dz = pos[dn * 3 + 2] - pos[sn * 3 + 2];
    float dist = sqrtf(dx * dx + dy * dy + dz * dz + EPSF);
    float4 eav = *(const float4*)&ea[e * 4];
    d_e1[e] = make_float4(dist, eav.x, eav.y, eav.z);
    float inv = 1.f / dist;
    d_e2[e] = make_float4(eav.w, dx * inv, dy * inv, dz * inv);
    atomicAdd(&d_cnt[dn], 1.f);
}

// ---------------- embedding ----------------
__global__ void embed_kernel(const float* __restrict__ x, const float* __restrict__ pos,
                             const float* __restrict__ Wes, const float* __restrict__ bes,
                             const float* __restrict__ Wev, int Nn) {
    int idx = blockIdx.x * blockDim.x + threadIdx.x;
    if (idx >= Nn * F) return;
    int n = idx / F, f = idx & (F - 1);
    float xs[5];
#pragma unroll
    for (int i = 0; i < 5; i++) xs[i] = x[n * 5 + i];
    float as = bes[f], av = 0.f;
#pragma unroll
    for (int i = 0; i < 5; i++) { as += xs[i] * Wes[i * F + f]; av += xs[i] * Wev[i * F + f]; }
    float px = pos[n * 3], py = pos[n * 3 + 1], pz = pos[n * 3 + 2];
    d_sv[idx] = make_float4(as, av * px, av * py, av * pz);
}

// ---------------- fused edge MLP (tf32 tensor-core GEMM2) + scatter ----------------
// 64-edge tile; GEMM1 writes h directly in B-fragment layout; 6 mma warps hold
// W2 A-fragments in registers across the whole kernel; scatter lane = feature.
#define BPLANE 2112          // 64 blocks * 33 floats
#define GPITCH 66            // g_smem row pitch (floats)

__global__ void __launch_bounds__(256, 3) msg_kernel(
    const int* __restrict__ ei,
    const float* __restrict__ W1, const float* __restrict__ b1,
    const float* __restrict__ W2, const float* __restrict__ b2, int E) {
    __shared__ float sW1[5 * H];          // 320
    __shared__ float sb1[H];              // 64
    __shared__ float sb2[3 * F];          // 96
    __shared__ float sEIn[TILE * 5];      // 320
    __shared__ float4 sU4[TILE];          // 256
    __shared__ int2 sSD[TILE];            // 128
    __shared__ unsigned int bP[2 * BPLANE];  // 4224 : B fragment planes (tf32)
    __shared__ float gS[96 * GPITCH];     // 6336 : g outputs [out][edge]

    int tid = threadIdx.x;
    int w = tid >> 5;
    int lane = tid & 31;
    int g = lane >> 2;      // mma groupID
    int tg = lane & 3;      // mma threadID-in-group

    for (int i = tid; i < 5 * H; i += 256) sW1[i] = W1[i];
    if (tid < H) sb1[tid] = b1[tid];
    if (tid < 96) sb2[tid] = b2[tid];

    // A fragments: warps 0..5 own out-strip m0 = w*16, held in registers.
    unsigned int a0[8], a1[8], a2[8], a3[8];
    float bias0 = 0.f, bias1 = 0.f;
    if (w < 6) {
        int m0 = w * 16;
#pragma unroll
        for (int kt = 0; kt < 8; kt++) {
            int k0 = kt * 8 + tg;
            a0[kt] = to_tf32(W2[k0 * 96 + m0 + g]);
            a1[kt] = to_tf32(W2[k0 * 96 + m0 + 8 + g]);
            a2[kt] = to_tf32(W2[(k0 + 4) * 96 + m0 + g]);
            a3[kt] = to_tf32(W2[(k0 + 4) * 96 + m0 + 8 + g]);
        }
        bias0 = b2[m0 + g];
        bias1 = b2[m0 + 8 + g];
    }

    int eBase = w * 8;      // scatter: warp owns 8 edges

    int ntiles = (E + TILE - 1) / TILE;
    for (int t = blockIdx.x; t < ntiles; t += gridDim.x) {
        int e0 = t * TILE;
        __syncthreads();  // previous tile fully consumed
        if (tid < TILE) {
            int e = e0 + tid;
            if (e < E) {
                sSD[tid] = make_int2(ei[e], ei[E + e]);
                float4 e1 = d_e1[e];
                float4 e2 = d_e2[e];
                sEIn[tid * 5 + 0] = e1.x;
                sEIn[tid * 5 + 1] = e1.y;
                sEIn[tid * 5 + 2] = e1.z;
                sEIn[tid * 5 + 3] = e1.w;
                sEIn[tid * 5 + 4] = e2.x;
                sU4[tid] = make_float4(e2.y, e2.z, e2.w, 0.f);
            } else {
                sSD[tid] = make_int2(0, 0);
#pragma unroll
                for (int i = 0; i < 5; i++) sEIn[tid * 5 + i] = 0.f;
                sU4[tid] = make_float4(0.f, 0.f, 0.f, 0.f);
            }
        }
        __syncthreads();

        // GEMM1: h[e][c] = elu(b1[c] + edge_in[e].W1[:,c]) -> tf32 -> B-fragment planes
        {
            int e = tid & (TILE - 1);
            int cgrp = tid >> 6;  // 0..3 -> 16 cols each
            float ein[5];
#pragma unroll
            for (int i = 0; i < 5; i++) ein[i] = sEIn[e * 5 + i];
            int nt8 = (e >> 3) * 8;
            int ge = e & 7;
#pragma unroll
            for (int cc = 0; cc < 16; cc++) {
                int c = cgrp * 16 + cc;
                float a = sb1[c];
#pragma unroll
                for (int i = 0; i < 5; i++) a += ein[i] * sW1[i * H + c];
                float hv = a > 0.f ? a : (__expf(a) - 1.f);
                // fragment slot: plane j=(c>>2)&1, block (nt*8 + kt), inner (c&3)*8 + (e&7)
                int slot = ((c >> 2) & 1) * BPLANE + (nt8 + (c >> 3)) * 33 + (c & 3) * 8 + ge;
                bP[slot] = to_tf32(hv);
            }
        }
        __syncthreads();

        // GEMM2 via tensor cores: warps 0..5, g[96][64] = W2^T @ h + b2
        if (w < 6) {
            int m0 = w * 16;
            int fragInner = tg * 8 + g;  // conflict-free B read pattern
#pragma unroll
            for (int nt = 0; nt < 8; nt++) {
                float c0 = bias0, c1 = bias0, c2 = bias1, c3 = bias1;
#pragma unroll
                for (int kt = 0; kt < 8; kt++) {
                    int slot = (nt * 8 + kt) * 33 + fragInner;
                    unsigned int bb0 = bP[slot];
                    unsigned int bb1 = bP[BPLANE + slot];
                    mma_tf32(c0, c1, c2, c3, a0[kt], a1[kt], a2[kt], a3[kt], bb0, bb1);
                }
                int col = nt * 8 + 2 * tg;
                *(float2*)&gS[(m0 + g) * GPITCH + col] = make_float2(c0, c1);
                *(float2*)&gS[(m0 + 8 + g) * GPITCH + col] = make_float2(c2, c3);
            }
        }
        __syncthreads();

        // scatter: per edge, lane = f -> coalesced LDG.128 + RED.v4
        int f = lane;
#pragma unroll
        for (int i = 0; i < 8; i++) {
            int e = eBase + i;
            if (e0 + e >= E) continue;
            float gs = gS[f * GPITCH + e];
            float gv = gS[(32 + f) * GPITCH + e];
            float gx = gS[(64 + f) * GPITCH + e];
            int2 sd = sSD[e];
            float4 u = sU4[e];
            float4 sv = d_sv[sd.x * F + f];   // coalesced across lanes
            float c = gx * sv.x;
            red_add_v4(&d_acc[sd.y * F + f],  // coalesced across lanes
                       gs * sv.x,
                       gv * sv.y + c * u.x,
                       gv * sv.z + c * u.y,
                       gv * sv.w + c * u.z);
        }
    }
}

// ---------------- node update: s += elu(as@Ws); v += av@Wv ----------------
__global__ void __launch_bounds__(256) upd_kernel(const float* __restrict__ Ws,
                                                  const float* __restrict__ Wv, int Nn) {
    __shared__ float sWs[F * F], sWv[F * F];
    __shared__ float4 sA[8][F];
    int tid = threadIdx.x;
    for (int i = tid; i < F * F; i += 256) { sWs[i] = Ws[i]; sWv[i] = Wv[i]; }
    int ln = tid >> 5, f = tid & 31;
    int n = blockIdx.x * 8 + ln;
    bool ok = n < Nn;
    if (ok) {
        float inv = 1.f / fmaxf(d_cnt[n], 1.f);
        float4 a = d_acc[n * F + f];
        sA[ln][f] = make_float4(a.x * inv, a.y * inv, a.z * inv, a.w * inv);
        d_acc[n * F + f] = make_float4(0.f, 0.f, 0.f, 0.f);  // ready for next layer
    }
    __syncthreads();
    if (ok) {
        float a = 0, vx = 0, vy = 0, vz = 0;
#pragma unroll
        for (int g = 0; g < F; g++) {
            float w1 = sWs[g * F + f], w2 = sWv[g * F + f];
            float4 ag = sA[ln][g];
            a  += ag.x * w1;
            vx += ag.y * w2;
            vy += ag.z * w2;
            vz += ag.w * w2;
        }
        float4 cur = d_sv[n * F + f];
        cur.x += elu1(a);
        cur.y += vx;
        cur.z += vy;
        cur.w += vz;
        d_sv[n * F + f] = cur;
    }
}

// ---------------- graph node counts ----------------
__global__ void gcnt_kernel(const int* __restrict__ batch, int Nn) {
    int n = blockIdx.x * blockDim.x + threadIdx.x;
    if (n < Nn) atomicAdd(&d_gcnt[batch[n]], 1.f);
}

// ---------------- invariant map + graph-sum pooling ----------------
__global__ void __launch_bounds__(128) inv_kernel(const int* __restrict__ batch,
                                                  const float* __restrict__ Winv,
                                                  const float* __restrict__ binv, int Nn) {
    __shared__ float sW[2 * F * NINVC];  // 32KB
    __shared__ float sFeat[2 * F];
    int tid = threadIdx.x;
    for (int i = tid; i < 2 * F * NINVC; i += 128) sW[i] = Winv[i];
    float bj = binv[tid];
    int n0 = blockIdx.x * 32;
    for (int nn = 0; nn < 32; nn++) {
        int n = n0 + nn;
        if (n >= Nn) break;
        __syncthreads();
        if (tid < F) {
            float4 sv = d_sv[n * F + tid];
            sFeat[tid] = sv.x;
            sFeat[F + tid] = sqrtf(sv.y * sv.y + sv.z * sv.z + sv.w * sv.w + EPSF);
        }
        __syncthreads();
        float acc = bj;
#pragma unroll 8
        for (int i = 0; i < 2 * F; i++) acc += sFeat[i] * sW[i * NINVC + tid];
        atomicAdd(&d_xgsum[batch[n] * NINVC + tid], acc);
    }
}

// ---------------- mean pool finalize ----------------
__global__ void poolfin_kernel(int G) {
    int i = blockIdx.x * blockDim.x + threadIdx.x;
    if (i < G * NINVC) d_xg[i] = d_xgsum[i] / fmaxf(d_gcnt[i / NINVC], 1.f);
}

// ---------------- batchnorm column stats ----------------
__global__ void bnstats_kernel(int which, int G) {
    const float* z = which ? d_z1 : d_xg;
    float* mean = which ? d_m2 : d_m1;
    float* rstd = which ? d_r2 : d_r1;
    int j = blockIdx.x;
    __shared__ float sS[256], sQ[256];
    float s = 0.f, q = 0.f;
    for (int g = threadIdx.x; g < G; g += 256) {
        float val = z[g * NINVC + j];
        s += val; q += val * val;
    }
    sS[threadIdx.x] = s; sQ[threadIdx.x] = q;
    __syncthreads();
    for (int off = 128; off > 0; off >>= 1) {
        if (threadIdx.x < off) { sS[threadIdx.x] += sS[threadIdx.x + off]; sQ[threadIdx.x] += sQ[threadIdx.x + off]; }
        __syncthreads();
    }
    if (threadIdx.x == 0) {
        float m = sS[0] / (float)G;
        float var = sQ[0] / (float)G - m * m;
        mean[j] = m;
        rstd[j] = rsqrtf(var + 1e-5f);
    }
}

// ---------------- fc1 ----------------
__global__ void __launch_bounds__(128) fc1_kernel(const float* __restrict__ Wf1,
                                                  const float* __restrict__ bf1,
                                                  const float* __restrict__ g1,
                                                  const float* __restrict__ be1, int G) {
    __shared__ float sA[NINVC];
    int tid = threadIdx.x;
    float gj = g1[tid], bej = be1[tid], mj = d_m1[tid], rj = d_r1[tid], bfj = bf1[tid];
    int r0 = blockIdx.x * 16;
    for (int rr = 0; rr < 16; rr++) {
        int r = r0 + rr;
        if (r >= G) break;
        __syncthreads();
        float a = (d_xg[r * NINVC + tid] - mj) * rj * gj + bej;
        sA[tid] = elu1(a);
        __syncthreads();
        float acc = bfj;
#pragma unroll 8
        for (int i = 0; i < NINVC; i++) acc += sA[i] * Wf1[i * NINVC + tid];
        d_z1[r * NINVC + tid] = acc;
    }
}

// ---------------- fc2 ----------------
__global__ void fc2_kernel(const float* __restrict__ Wf2, const float* __restrict__ bf2,
                           const float* __restrict__ g2, const float* __restrict__ be2,
                           float* __restrict__ out, int G) {
    int warp = threadIdx.x >> 5, lane = threadIdx.x & 31;
    int r = blockIdx.x * 8 + warp;
    if (r >= G) return;
    float acc = 0.f;
    for (int j = lane; j < NINVC; j += 32) {
        float a = (d_z1[r * NINVC + j] - d_m2[j]) * d_r2[j] * g2[j] + be2[j];
        acc += elu1(a) * Wf2[j];
    }
#pragma unroll
    for (int off = 16; off > 0; off >>= 1) acc += __shfl_down_sync(0xffffffffu, acc, off);
    if (lane == 0) out[r] = acc + bf2[0];
}

// ---------------- launch ----------------
extern "C" void kernel_launch(void* const* d_in, const int* in_sizes, int n_in,
                              void* d_out, int out_size) {
    const float* x     = (const float*)d_in[0];
    const float* pos   = (const float*)d_in[1];
    const int*   ei    = (const int*)d_in[2];
    const float* ea    = (const float*)d_in[3];
    const int*   batch = (const int*)d_in[4];
    const float* Wes   = (const float*)d_in[5];
    const float* bes   = (const float*)d_in[6];
    const float* Wev   = (const float*)d_in[7];
    const float* W1    = (const float*)d_in[8];
    const float* b1    = (const float*)d_in[9];
    const float* W2    = (const float*)d_in[10];
    const float* b2    = (const float*)d_in[11];
    const float* Ws    = (const float*)d_in[12];
    const float* Wv    = (const float*)d_in[13];
    const float* Winv  = (const float*)d_in[14];
    const float* binv  = (const float*)d_in[15];
    const float* g1    = (const float*)d_in[16];
    const float* be1   = (const float*)d_in[17];
    const float* Wf1   = (const float*)d_in[18];
    const float* bf1   = (const float*)d_in[19];
    const float* g2    = (const float*)d_in[20];
    const float* be2   = (const float*)d_in[21];
    const float* Wf2   = (const float*)d_in[22];
    const float* bf2   = (const float*)d_in[23];

    int Nn = in_sizes[0] / 5;
    int E  = in_sizes[2] / 2;
    int G  = out_size;
    float* out = (float*)d_out;

    zero_kernel<<<2048, 256>>>();
    prep_kernel<<<(E + 255) / 256, 256>>>(pos, ei, ea, E);
    embed_kernel<<<(Nn * F + 255) / 256, 256>>>(x, pos, Wes, bes, Wev, Nn);

    for (int l = 0; l < 4; l++) {
        msg_kernel<<<1480, 256>>>(ei,
                                  W1 + l * 5 * H, b1 + l * H,
                                  W2 + l * H * 3 * F, b2 + l * 3 * F, E);
        upd_kernel<<<(Nn + 7) / 8, 256>>>(Ws + l * F * F, Wv + l * F * F, Nn);
    }

    gcnt_kernel<<<(Nn + 255) / 256, 256>>>(batch, Nn);
    inv_kernel<<<(Nn + 31) / 32, 128>>>(batch, Winv, binv, Nn);
    poolfin_kernel<<<(G * NINVC + 255) / 256, 256>>>(G);
    bnstats_kernel<<<NINVC, 256>>>(0, G);
    fc1_kernel<<<(G + 15) / 16, 128>>>(Wf1, bf1, g1, be1, G);
    bnstats_kernel<<<NINVC, 256>>>(1, G);
    fc2_kernel<<<(G + 7) / 8, 256>>>(Wf2, bf2, g2, be2, out, G);
}

// round 14
// speedup vs baseline: 1.1840x; 1.0047x over previous
#include <cuda_runtime.h>
#include <math.h>

#define NN 50000
#define EE 800000
#define F 32
#define H 64
#define NINVC 128
#define GMAX 2048
#define EPSF 1e-6f
#define TILE 64

// ---------------- scratch (device globals; no allocation) ----------------
__device__ float4 d_sv[NN * F];    // packed node state {s, vx, vy, vz}
__device__ float4 d_acc[NN * F];   // packed accumulator {as, avx, avy, avz}
__device__ float d_cnt[NN];
__device__ float4 d_e1[EE];        // {dist, ea0, ea1, ea2}
__device__ float4 d_e2[EE];        // {ea3, ux, uy, uz}
__device__ float d_xgsum[GMAX * NINVC];
__device__ float d_gcnt[GMAX];
__device__ float d_xg[GMAX * NINVC];
__device__ float d_z1[GMAX * NINVC];
__device__ float d_m1[NINVC];
__device__ float d_r1[NINVC];
__device__ float d_m2[NINVC];
__device__ float d_r2[NINVC];

__device__ __forceinline__ float elu1(float x) { return x > 0.f ? x : expm1f(x); }

__device__ __forceinline__ void red_add_v4(float4* addr, float a, float b, float c, float d) {
    asm volatile("red.global.add.v4.f32 [%0], {%1, %2, %3, %4};"
                 :: "l"(addr), "f"(a), "f"(b), "f"(c), "f"(d) : "memory");
}

__device__ __forceinline__ unsigned int to_tf32(float x) {
    unsigned int u;
    asm("cvt.rna.tf32.f32 %0, %1;" : "=r"(u) : "f"(x));
    return u;
}

__device__ __forceinline__ void mma_tf32(float& c0, float& c1, float& c2, float& c3,
                                         unsigned int a0, unsigned int a1,
                                         unsigned int a2, unsigned int a3,
                                         unsigned int b0, unsigned int b1) {
    asm volatile(
        "mma.sync.aligned.m16n8k8.row.col.f32.tf32.tf32.f32 "
        "{%0,%1,%2,%3}, {%4,%5,%6,%7}, {%8,%9}, {%0,%1,%2,%3};"
        : "+f"(c0), "+f"(c1), "+f"(c2), "+f"(c3)
        : "r"(a0), "r"(a1), "r"(a2), "r"(a3), "r"(b0), "r"(b1));
}

// ---------------- zero accumulators ----------------
__global__ void zero_kernel() {
    int stride = gridDim.x * blockDim.x;
    float4 z4 = make_float4(0.f, 0.f, 0.f, 0.f);
    for (int i = blockIdx.x * blockDim.x + threadIdx.x; i < NN * F; i += stride) {
        d_acc[i] = z4;
        if (i < NN) d_cnt[i] = 0.f;
        if (i < GMAX * NINVC) d_xgsum[i] = 0.f;
        if (i < GMAX) d_gcnt[i] = 0.f;
    }
}

// ---------------- one-time edge geometry + degree ----------------
__global__ void prep_kernel(const float* __restrict__ pos, const int* __restrict__ ei,
                            const float* __restrict__ ea, int E) {
    int e = blockIdx.x * blockDim.x + threadIdx.x;
    if (e >= E) return;
    int sn = ei[e], dn = ei[E + e];
    float dx = pos[dn * 3 + 0] - pos[sn * 3 + 0];
    float dy = pos[dn * 3 + 1] - pos[sn * 3 + 1];
    float dz = pos[dn * 3 + 2] - pos[sn * 3 + 2];
    float dist = sqrtf(dx * dx + dy * dy + dz * dz + EPSF);
    float4 eav = *(const float4*)&ea[e * 4];
    d_e1[e] = make_float4(dist, eav.x, eav.y, eav.z);
    float inv = 1.f / dist;
    d_e2[e] = make_float4(eav.w, dx * inv, dy * inv, dz * inv);
    atomicAdd(&d_cnt[dn], 1.f);
}

// ---------------- embedding ----------------
__global__ void embed_kernel(const float* __restrict__ x, const float* __restrict__ pos,
                             const float* __restrict__ Wes, const float* __restrict__ bes,
                             const float* __restrict__ Wev, int Nn) {
    int idx = blockIdx.x * blockDim.x + threadIdx.x;
    if (idx >= Nn * F) return;
    int n = idx / F, f = idx & (F - 1);
    float xs[5];
#pragma unroll
    for (int i = 0; i < 5; i++) xs[i] = x[n * 5 + i];
    float as = bes[f], av = 0.f;
#pragma unroll
    for (int i = 0; i < 5; i++) { as += xs[i] * Wes[i * F + f]; av += xs[i] * Wev[i * F + f]; }
    float px = pos[n * 3], py = pos[n * 3 + 1], pz = pos[n * 3 + 2];
    d_sv[idx] = make_float4(as, av * px, av * py, av * pz);
}

// ---------------- fused edge MLP (tf32 mma) + scatter, warp-local pipeline ----------------
#define BPLANE 2112          // 64 blocks * 33 floats
#define GPITCH 66            // g_smem row pitch (floats)

__global__ void __launch_bounds__(256, 3) msg_kernel(
    const int* __restrict__ ei,
    const float* __restrict__ W1, const float* __restrict__ b1,
    const float* __restrict__ W2, const float* __restrict__ b2, int E) {
    __shared__ float sE8[2][TILE * 8];       // per-edge: {dist,ea0..ea2 | ea3,ux,uy,uz}
    __shared__ int sS_[2][TILE];
    __shared__ int sD_[2][TILE];
    __shared__ unsigned int bP[2 * BPLANE];  // B fragment planes (tf32)
    __shared__ float gS[96 * GPITCH];        // g outputs [out][edge]

    int tid = threadIdx.x;
    int w = tid >> 5;
    int lane = tid & 31;
    int g = lane >> 2;      // mma groupID
    int tg = lane & 3;      // mma threadID-in-group
    int eBase = w * 8;      // warp owns these 8 edges (load, GEMM1, scatter)

    // W1/b1 in registers: thread covers c0=lane, c1=lane+32
    float w1r[5][2], b1r[2];
#pragma unroll
    for (int i = 0; i < 5; i++) {
        w1r[i][0] = W1[i * H + lane];
        w1r[i][1] = W1[i * H + lane + 32];
    }
    b1r[0] = b1[lane];
    b1r[1] = b1[lane + 32];

    // A fragments: warps 0..5 own out-strip m0 = w*16, held in registers.
    unsigned int a0[8], a1[8], a2[8], a3[8];
    float bias0 = 0.f, bias1 = 0.f;
    if (w < 6) {
        int m0 = w * 16;
#pragma unroll
        for (int kt = 0; kt < 8; kt++) {
            int k0 = kt * 8 + tg;
            a0[kt] = to_tf32(W2[k0 * 96 + m0 + g]);
            a1[kt] = to_tf32(W2[k0 * 96 + m0 + 8 + g]);
            a2[kt] = to_tf32(W2[(k0 + 4) * 96 + m0 + g]);
            a3[kt] = to_tf32(W2[(k0 + 4) * 96 + m0 + 8 + g]);
        }
        bias0 = b2[m0 + g];
        bias1 = b2[m0 + 8 + g];
    }

    int ntiles = (E + TILE - 1) / TILE;

    // warp-local edge prefetch into buffer pb for tile t (no block sync needed)
    int li = lane & 7, part = lane >> 3;
    auto fetch = [&](int t, int pb) {
        if (t >= ntiles) return;
        int e = t * TILE + eBase + li;
        bool ok = e < E;
        if (part == 0) {
            float4 v = ok ? d_e1[e] : make_float4(0.f, 0.f, 0.f, 0.f);
            *(float4*)&sE8[pb][(eBase + li) * 8] = v;
        } else if (part == 1) {
            float4 v = ok ? d_e2[e] : make_float4(0.f, 0.f, 0.f, 0.f);
            *(float4*)&sE8[pb][(eBase + li) * 8 + 4] = v;
        } else if (part == 2) {
            sS_[pb][eBase + li] = ok ? ei[e] : 0;
        } else {
            sD_[pb][eBase + li] = ok ? ei[E + e] : 0;
        }
    };

    fetch(blockIdx.x, 0);
    __syncwarp();

    int buf = 0;
    for (int t = blockIdx.x; t < ntiles; t += gridDim.x) {
        int e0 = t * TILE;

        // GEMM1 (warp-local): h for edges eBase..+7, c = lane and lane+32
#pragma unroll
        for (int i = 0; i < 8; i++) {
            float4 q1 = *(const float4*)&sE8[buf][(eBase + i) * 8];     // broadcast
            float q2 = sE8[buf][(eBase + i) * 8 + 4];                    // broadcast
            float acc0 = b1r[0] + q1.x * w1r[0][0] + q1.y * w1r[1][0] + q1.z * w1r[2][0]
                       + q1.w * w1r[3][0] + q2 * w1r[4][0];
            float acc1 = b1r[1] + q1.x * w1r[0][1] + q1.y * w1r[1][1] + q1.z * w1r[2][1]
                       + q1.w * w1r[3][1] + q2 * w1r[4][1];
            float h0 = acc0 > 0.f ? acc0 : (__expf(acc0) - 1.f);
            float h1 = acc1 > 0.f ? acc1 : (__expf(acc1) - 1.f);
            // fragment slot: plane=(c>>2)&1, block=(e>>3)*8+(c>>3), inner=(c&3)*8+(e&7)
            int base = w * 8 * 33 + (lane & 3) * 8 + i;
            int pl = (lane >> 2) & 1;
            bP[pl * BPLANE + base + (lane >> 3) * 33] = to_tf32(h0);
            bP[pl * BPLANE + base + (4 + (lane >> 3)) * 33] = to_tf32(h1);
        }

        // prefetch next tile's edge data (overlaps mma + scatter)
        fetch(t + gridDim.x, buf ^ 1);

        __syncthreads();  // bP complete (prev consumers finished at loop-end sync)

        // GEMM2 via tensor cores: warps 0..5, g[96][64] = W2^T @ h + b2
        if (w < 6) {
            int m0 = w * 16;
            int fragInner = tg * 8 + g;  // conflict-free B read pattern
#pragma unroll
            for (int nt = 0; nt < 8; nt++) {
                float c0 = bias0, c1 = bias0, c2 = bias1, c3 = bias1;
#pragma unroll
                for (int kt = 0; kt < 8; kt++) {
                    int slot = (nt * 8 + kt) * 33 + fragInner;
                    unsigned int bb0 = bP[slot];
                    unsigned int bb1 = bP[BPLANE + slot];
                    mma_tf32(c0, c1, c2, c3, a0[kt], a1[kt], a2[kt], a3[kt], bb0, bb1);
                }
                int col = nt * 8 + 2 * tg;
                *(float2*)&gS[(m0 + g) * GPITCH + col] = make_float2(c0, c1);
                *(float2*)&gS[(m0 + 8 + g) * GPITCH + col] = make_float2(c2, c3);
            }
        }
        __syncthreads();  // gS complete

        // scatter (warp-local edges): lane = f -> coalesced LDG.128 + RED.v4
        int f = lane;
#pragma unroll
        for (int i = 0; i < 8; i++) {
            int e = eBase + i;
            if (e0 + e >= E) continue;
            float gs = gS[f * GPITCH + e];
            float gv = gS[(32 + f) * GPITCH + e];
            float gx = gS[(64 + f) * GPITCH + e];
            int sn = sS_[buf][e];                         // broadcast
            int dn = sD_[buf][e];                         // broadcast
            float4 u = *(const float4*)&sE8[buf][e * 8 + 4];  // broadcast {ea3,ux,uy,uz}
            float4 sv = d_sv[sn * F + f];   // coalesced across lanes
            float c = gx * sv.x;
            red_add_v4(&d_acc[dn * F + f],  // coalesced across lanes
                       gs * sv.x,
                       gv * sv.y + c * u.y,
                       gv * sv.z + c * u.z,
                       gv * sv.w + c * u.w);
        }
        __syncthreads();  // gS/bP free for next iteration
        buf ^= 1;
    }
}

// ---------------- node update: s += elu(as@Ws); v += av@Wv ----------------
__global__ void __launch_bounds__(256) upd_kernel(const float* __restrict__ Ws,
                                                  const float* __restrict__ Wv, int Nn) {
    __shared__ float sWs[F * F], sWv[F * F];
    __shared__ float4 sA[8][F];
    int tid = threadIdx.x;
    for (int i = tid; i < F * F; i += 256) { sWs[i] = Ws[i]; sWv[i] = Wv[i]; }
    int ln = tid >> 5, f = tid & 31;
    int n = blockIdx.x * 8 + ln;
    bool ok = n < Nn;
    if (ok) {
        float inv = 1.f / fmaxf(d_cnt[n], 1.f);
        float4 a = d_acc[n * F + f];
        sA[ln][f] = make_float4(a.x * inv, a.y * inv, a.z * inv, a.w * inv);
        d_acc[n * F + f] = make_float4(0.f, 0.f, 0.f, 0.f);  // ready for next layer
    }
    __syncthreads();
    if (ok) {
        float a = 0, vx = 0, vy = 0, vz = 0;
#pragma unroll
        for (int g = 0; g < F; g++) {
            float w1 = sWs[g * F + f], w2 = sWv[g * F + f];
            float4 ag = sA[ln][g];
            a  += ag.x * w1;
            vx += ag.y * w2;
            vy += ag.z * w2;
            vz += ag.w * w2;
        }
        float4 cur = d_sv[n * F + f];
        cur.x += elu1(a);
        cur.y += vx;
        cur.z += vy;
        cur.w += vz;
        d_sv[n * F + f] = cur;
    }
}

// ---------------- graph node counts ----------------
__global__ void gcnt_kernel(const int* __restrict__ batch, int Nn) {
    int n = blockIdx.x * blockDim.x + threadIdx.x;
    if (n < Nn) atomicAdd(&d_gcnt[batch[n]], 1.f);
}

// ---------------- invariant map + graph-sum pooling ----------------
__global__ void __launch_bounds__(128) inv_kernel(const int* __restrict__ batch,
                                                  const float* __restrict__ Winv,
                                                  const float* __restrict__ binv, int Nn) {
    __shared__ float sW[2 * F * NINVC];  // 32KB
    __shared__ float sFeat[2 * F];
    int tid = threadIdx.x;
    for (int i = tid; i < 2 * F * NINVC; i += 128) sW[i] = Winv[i];
    float bj = binv[tid];
    int n0 = blockIdx.x * 32;
    for (int nn = 0; nn < 32; nn++) {
        int n = n0 + nn;
        if (n >= Nn) break;
        __syncthreads();
        if (tid < F) {
            float4 sv = d_sv[n * F + tid];
            sFeat[tid] = sv.x;
            sFeat[F + tid] = sqrtf(sv.y * sv.y + sv.z * sv.z + sv.w * sv.w + EPSF);
        }
        __syncthreads();
        float acc = bj;
#pragma unroll 8
        for (int i = 0; i < 2 * F; i++) acc += sFeat[i] * sW[i * NINVC + tid];
        atomicAdd(&d_xgsum[batch[n] * NINVC + tid], acc);
    }
}

// ---------------- mean pool finalize ----------------
__global__ void poolfin_kernel(int G) {
    int i = blockIdx.x * blockDim.x + threadIdx.x;
    if (i < G * NINVC) d_xg[i] = d_xgsum[i] / fmaxf(d_gcnt[i / NINVC], 1.f);
}

// ---------------- batchnorm column stats ----------------
__global__ void bnstats_kernel(int which, int G) {
    const float* z = which ? d_z1 : d_xg;
    float* mean = which ? d_m2 : d_m1;
    float* rstd = which ? d_r2 : d_r1;
    int j = blockIdx.x;
    __shared__ float sS[256], sQ[256];
    float s = 0.f, q = 0.f;
    for (int g = threadIdx.x; g < G; g += 256) {
        float val = z[g * NINVC + j];
        s += val; q += val * val;
    }
    sS[threadIdx.x] = s; sQ[threadIdx.x] = q;
    __syncthreads();
    for (int off = 128; off > 0; off >>= 1) {
        if (threadIdx.x < off) { sS[threadIdx.x] += sS[threadIdx.x + off]; sQ[threadIdx.x] += sQ[threadIdx.x + off]; }
        __syncthreads();
    }
    if (threadIdx.x == 0) {
        float m = sS[0] / (float)G;
        float var = sQ[0] / (float)G - m * m;
        mean[j] = m;
        rstd[j] = rsqrtf(var + 1e-5f);
    }
}

// ---------------- fc1 ----------------
__global__ void __launch_bounds__(128) fc1_kernel(const float* __restrict__ Wf1,
                                                  const float* __restrict__ bf1,
                                                  const float* __restrict__ g1,
                                                  const float* __restrict__ be1, int G) {
    __shared__ float sA[NINVC];
    int tid = threadIdx.x;
    float gj = g1[tid], bej = be1[tid], mj = d_m1[tid], rj = d_r1[tid], bfj = bf1[tid];
    int r0 = blockIdx.x * 16;
    for (int rr = 0; rr < 16; rr++) {
        int r = r0 + rr;
        if (r >= G) break;
        __syncthreads();
        float a = (d_xg[r * NINVC + tid] - mj) * rj * gj + bej;
        sA[tid] = elu1(a);
        __syncthreads();
        float acc = bfj;
#pragma unroll 8
        for (int i = 0; i < NINVC; i++) acc += sA[i] * Wf1[i * NINVC + tid];
        d_z1[r * NINVC + tid] = acc;
    }
}

// ---------------- fc2 ----------------
__global__ void fc2_kernel(const float* __restrict__ Wf2, const float* __restrict__ bf2,
                           const float* __restrict__ g2, const float* __restrict__ be2,
                           float* __restrict__ out, int G) {
    int warp = threadIdx.x >> 5, lane = threadIdx.x & 31;
    int r = blockIdx.x * 8 + warp;
    if (r >= G) return;
    float acc = 0.f;
    for (int j = lane; j < NINVC; j += 32) {
        float a = (d_z1[r * NINVC + j] - d_m2[j]) * d_r2[j] * g2[j] + be2[j];
        acc += elu1(a) * Wf2[j];
    }
#pragma unroll
    for (int off = 16; off > 0; off >>= 1) acc += __shfl_down_sync(0xffffffffu, acc, off);
    if (lane == 0) out[r] = acc + bf2[0];
}

// ---------------- launch ----------------
extern "C" void kernel_launch(void* const* d_in, const int* in_sizes, int n_in,
                              void* d_out, int out_size) {
    const float* x     = (const float*)d_in[0];
    const float* pos   = (const float*)d_in[1];
    const int*   ei    = (const int*)d_in[2];
    const float* ea    = (const float*)d_in[3];
    const int*   batch = (const int*)d_in[4];
    const float* Wes   = (const float*)d_in[5];
    const float* bes   = (const float*)d_in[6];
    const float* Wev   = (const float*)d_in[7];
    const float* W1    = (const float*)d_in[8];
    const float* b1    = (const float*)d_in[9];
    const float* W2    = (const float*)d_in[10];
    const float* b2    = (const float*)d_in[11];
    const float* Ws    = (const float*)d_in[12];
    const float* Wv    = (const float*)d_in[13];
    const float* Winv  = (const float*)d_in[14];
    const float* binv  = (const float*)d_in[15];
    const float* g1    = (const float*)d_in[16];
    const float* be1   = (const float*)d_in[17];
    const float* Wf1   = (const float*)d_in[18];
    const float* bf1   = (const float*)d_in[19];
    const float* g2    = (const float*)d_in[20];
    const float* be2   = (const float*)d_in[21];
    const float* Wf2   = (const float*)d_in[22];
    const float* bf2   = (const float*)d_in[23];

    int Nn = in_sizes[0] / 5;
    int E  = in_sizes[2] / 2;
    int G  = out_size;
    float* out = (float*)d_out;

    zero_kernel<<<2048, 256>>>();
    prep_kernel<<<(E + 255) / 256, 256>>>(pos, ei, ea, E);
    embed_kernel<<<(Nn * F + 255) / 256, 256>>>(x, pos, Wes, bes, Wev, Nn);

    for (int l = 0; l < 4; l++) {
        msg_kernel<<<1480, 256>>>(ei,
                                  W1 + l * 5 * H, b1 + l * H,
                                  W2 + l * H * 3 * F, b2 + l * 3 * F, E);
        upd_kernel<<<(Nn + 7) / 8, 256>>>(Ws + l * F * F, Wv + l * F * F, Nn);
    }

    gcnt_kernel<<<(Nn + 255) / 256, 256>>>(batch, Nn);
    inv_kernel<<<(Nn + 31) / 32, 128>>>(batch, Winv, binv, Nn);
    poolfin_kernel<<<(G * NINVC + 255) / 256, 256>>>(G);
    bnstats_kernel<<<NINVC, 256>>>(0, G);
    fc1_kernel<<<(G + 15) / 16, 128>>>(Wf1, bf1, g1, be1, G);
    bnstats_kernel<<<NINVC, 256>>>(1, G);
    fc2_kernel<<<(G + 7) / 8, 256>>>(Wf2, bf2, g2, be2, out, G);
}